// round 14
// baseline (speedup 1.0000x reference)
#include <cuda_runtime.h>
#include <cstdint>

#define N 2304
#define BB 1024
#define FF 32
#define TEAM 72
#define NCTA (2 * TEAM)
#define NTHR 1024

#define CPS 9                       // chunks per step
#define CW 256                      // chunk extent along streamed dim
#define SLOT_FLOATS (32 * CW)       // 8192 floats = 32 KB
#define SLOT_BYTES (SLOT_FLOATS * 4)
#define RING 5
#define DEPTH 4
#define TOTAL (31 * CPS)            // 279 chunks per team member

// smem float offsets
#define OFF_V    (RING * SLOT_FLOATS)          // 40960
#define OFF_RED  (OFF_V + N)                   // 43264
#define OFF_MBAR (OFF_RED + 1056)              // 44320 (8B aligned)
#define SMEM_BYTES ((OFF_MBAR + 2 * RING) * 4) // 177320

// device scratch (no allocation allowed)
__device__ float g_v[FF * N];
__device__ float g_z[FF * N];
__device__ float g_keep[FF * N];
__device__ float g_vsum[TEAM];
__device__ int   g_cntF[64];
__device__ int   g_cntB[64];
__device__ int   g_cntAll;

__global__ void setup_kernel(const int* __restrict__ sel) {
    int tid = threadIdx.x;
    for (int i = tid; i < FF * N; i += NTHR) g_keep[i] = 1.0f;
    if (tid < 64) { g_cntF[tid] = 0; g_cntB[tid] = 0; }
    if (tid == 64) g_cntAll = 0;
    __syncthreads();
    if (tid < 256) {
        int f = sel[3 * tid];
        int node = sel[3 * tid + 1] * 64 + sel[3 * tid + 2];
        g_keep[f * N + node] = 0.0f;
    }
}

__device__ __forceinline__ void teambar(int* cnt, int s) {
    __threadfence();
    __syncthreads();
    if (threadIdx.x == 0) {
        atomicAdd(&cnt[s], 1);
        volatile int* c = &cnt[s];
        while (*c < TEAM) { }
        __threadfence();
    }
    __syncthreads();
}

__device__ __forceinline__ void mbar_init(uint32_t mb, uint32_t cnt) {
    asm volatile("mbarrier.init.shared.b64 [%0], %1;" :: "r"(mb), "r"(cnt) : "memory");
}
__device__ __forceinline__ void mbar_expect(uint32_t mb, uint32_t bytes) {
    asm volatile("mbarrier.arrive.expect_tx.shared.b64 _, [%0], %1;" :: "r"(mb), "r"(bytes) : "memory");
}
__device__ __forceinline__ void mbar_wait(uint32_t mb, uint32_t ph) {
    asm volatile("{\n\t.reg .pred p;\n\tWL_%=:\n\t"
        "mbarrier.try_wait.parity.acquire.cta.shared::cta.b64 p, [%0], %1, 0x989680;\n\t"
        "@p bra.uni WD_%=;\n\tbra.uni WL_%=;\n\tWD_%=:\n\t}"
        :: "r"(mb), "r"(ph) : "memory");
}
// 1-D bulk copy gmem->smem, completion via mbarrier complete_tx
__device__ __forceinline__ void bulkcp(uint32_t dst, const void* src, uint32_t bytes, uint32_t mb) {
    asm volatile("cp.async.bulk.shared::cluster.global.mbarrier::complete_tx::bytes [%0], [%1], %2, [%3];"
        :: "r"(dst), "l"(src), "r"(bytes), "r"(mb) : "memory");
}

// Persistent solver + fused final. 144 CTAs (1/SM), two teams of 72.
// CTAs 0..71:   forward  v_f = keep_f * (b_f + W[f-1] @ v_{f-1})   (32 rows each)
// CTAs 72..143: backward z_f = 1 + W[f]^T @ (keep_{f+1} * z_{f+1}) (32 cols each)
// Weights stream continuously via cp.async.bulk (few large ops -> no LSU
// issue ceiling), ring of 5 x 32KB chunks, 4 in flight, mbarrier completion.
__global__ void __launch_bounds__(NTHR, 1)
solve_kernel(const float* __restrict__ W, const float* __restrict__ B,
             const int* __restrict__ cand, float* __restrict__ out)
{
    extern __shared__ float smem[];
    float* s_slot = smem;
    float* s_v    = smem + OFF_V;
    float* s_red  = smem + OFF_RED;

    uint32_t sbase;
    asm("{ .reg .u64 t; cvta.to.shared.u64 t, %1; cvt.u32.u64 %0, t; }" : "=r"(sbase) : "l"(smem));
    uint32_t mbar = sbase + OFF_MBAR * 4;

    int tid = threadIdx.x;
    int cta = blockIdx.x;
    int warp = tid >> 5, lane = tid & 31;

    if (tid < RING) mbar_init(mbar + tid * 8, 1);
    __syncthreads();

    if (cta < TEAM) {
        // ================= FORWARD TEAM =================
        int r0 = cta * 32;
        float myacc = 0.f;

        // warp 0 only: chunk idx -> W[idx/9] rows r0..r0+31, col block (idx%9)*256
        auto issue = [&](int idx) {
            int slot = idx % RING;
            uint32_t mb = mbar + slot * 8;
            if (lane == 0) mbar_expect(mb, SLOT_BYTES);
            __syncwarp();
            int ff = idx / CPS, cc = idx - ff * CPS;
            const float* src = W + ((size_t)ff * N + r0 + lane) * N + cc * CW;
            uint32_t dst = sbase + (uint32_t)slot * SLOT_BYTES + (uint32_t)lane * 1024;
            bulkcp(dst, src, 1024, mb);          // one row-chunk per lane
        };

        int issued = 0;
        if (warp == 0)
            for (int i = 0; i < DEPTH; ++i) issue(i);
        issued = DEPTH;

        if (tid < 32) {
            int row = r0 + tid;
            float v = g_keep[row] * B[row];
            g_v[row] = v;
            myacc += v;
        }
        teambar(g_cntF, 0);

        for (int f = 1; f < FF; ++f) {
            for (int n = tid; n < N; n += NTHR) s_v[n] = g_v[(f - 1) * N + n];

            float acc = 0.f;
            int g0 = (f - 1) * CPS;
            #pragma unroll
            for (int c = 0; c < CPS; ++c) {
                int idx = g0 + c;
                if (tid == 0) mbar_wait(mbar + (idx % RING) * 8, (idx / RING) & 1);
                __syncthreads();                 // chunk visible to all; prev slot free
                if (warp == 0 && issued < TOTAL) issue(issued);
                issued++;

                const float4* wrow = (const float4*)(s_slot + (idx % RING) * SLOT_FLOATS + warp * CW);
                const float4* vv   = (const float4*)(s_v + c * CW);
                float4 w0 = wrow[lane],      v0 = vv[lane];
                float4 w1 = wrow[lane + 32], v1 = vv[lane + 32];
                acc += w0.x * v0.x + w0.y * v0.y + w0.z * v0.z + w0.w * v0.w;
                acc += w1.x * v1.x + w1.y * v1.y + w1.z * v1.z + w1.w * v1.w;
            }
            #pragma unroll
            for (int o = 16; o; o >>= 1)
                acc += __shfl_xor_sync(0xffffffffu, acc, o);
            int ra = r0 + warp;                  // warp owns one row
            if (lane == 0) {
                float va = g_keep[f * N + ra] * (B[f * N + ra] + acc);
                g_v[f * N + ra] = va;
                myacc += va;
            }
            if (f < FF - 1) teambar(g_cntF, f);
        }

        #pragma unroll
        for (int o = 16; o; o >>= 1) myacc += __shfl_xor_sync(0xffffffffu, myacc, o);
        if (lane == 0) s_red[warp] = myacc;
        __syncthreads();
        if (tid == 0) {
            float t = 0.f;
            #pragma unroll
            for (int w = 0; w < 32; ++w) t += s_red[w];
            g_vsum[cta] = t;
        }
    } else {
        // ================= BACKWARD TEAM =================
        int id = cta - TEAM;
        int c0 = id * 32;

        // warp 0 only: chunk idx -> W[30-idx/9] rows (idx%9)*256.., cols c0..c0+31
        auto issue = [&](int idx) {
            int slot = idx % RING;
            uint32_t mb = mbar + slot * 8;
            if (lane == 0) mbar_expect(mb, SLOT_BYTES);
            __syncwarp();
            int ff = 30 - idx / CPS, cc = idx - (30 - ff) * CPS;
            const float* base = W + ((size_t)ff * N + cc * CW) * N + c0;
            uint32_t dst = sbase + (uint32_t)slot * SLOT_BYTES;
            #pragma unroll
            for (int j = 0; j < 8; ++j) {        // 256 rows x 128B, 8 per lane
                int row = lane + j * 32;
                bulkcp(dst + (uint32_t)row * 128, base + (size_t)row * N, 128, mb);
            }
        };

        int issued = 0;
        if (warp == 0)
            for (int i = 0; i < DEPTH; ++i) issue(i);
        issued = DEPTH;

        if (tid < 32) g_z[31 * N + c0 + tid] = 1.0f;
        teambar(g_cntB, 0);

        for (int f = FF - 2; f >= 0; --f) {
            for (int n = tid; n < N; n += NTHR)
                s_v[n] = g_keep[(f + 1) * N + n] * g_z[(f + 1) * N + n];

            float p = 0.f;
            int g0 = (30 - f) * CPS;
            #pragma unroll
            for (int c = 0; c < CPS; ++c) {
                int idx = g0 + c;
                if (tid == 0) mbar_wait(mbar + (idx % RING) * 8, (idx / RING) & 1);
                __syncthreads();
                if (warp == 0 && issued < TOTAL) issue(issued);
                issued++;

                const float* sw = s_slot + (idx % RING) * SLOT_FLOATS;
                const float* vv = s_v + c * CW;
                #pragma unroll
                for (int j = 0; j < 8; ++j) {    // row r = warp + 32*j within chunk
                    int r = warp + j * 32;
                    p += sw[r * 32 + lane] * vv[r];
                }
            }
            __syncthreads();                     // all consumption done; s_red reuse safe
            s_red[lane * 33 + warp] = p;         // padded transpose
            __syncthreads();
            float q = s_red[warp * 33 + lane];   // warp w reduces col c0+w
            #pragma unroll
            for (int o = 16; o; o >>= 1)
                q += __shfl_xor_sync(0xffffffffu, q, o);
            if (lane == 0) g_z[f * N + c0 + warp] = 1.0f + q;
            if (f > 0) teambar(g_cntB, 31 - f);
        }
    }

    // ================= FUSED FINAL =================
    __threadfence();
    __syncthreads();
    if (tid == 0) atomicAdd(&g_cntAll, 1);
    if (cta == 0) {
        if (tid == 0) {
            volatile int* c = &g_cntAll;
            while (*c < NCTA) { }
            __threadfence();
        }
        __syncthreads();
        float t = (tid < TEAM) ? g_vsum[tid] : 0.f;
        if (tid < 128) {
            #pragma unroll
            for (int o = 16; o; o >>= 1) t += __shfl_xor_sync(0xffffffffu, t, o);
            if ((tid & 31) == 0) s_red[tid >> 5] = t;
        }
        __syncthreads();
        if (tid == 0) s_red[0] = s_red[0] + s_red[1] + s_red[2] + s_red[3];
        __syncthreads();
        float TOT = s_red[0];
        int cf = cand[3 * tid];
        int cn = cand[3 * tid + 1] * 64 + cand[3 * tid + 2];
        out[tid] = TOT - g_v[cf * N + cn] * g_z[cf * N + cn];
    }
}

extern "C" void kernel_launch(void* const* d_in, const int* in_sizes, int n_in,
                              void* d_out, int out_size) {
    const float* weights = (const float*)d_in[0];
    const float* biases  = (const float*)d_in[1];
    const int*   sel     = (const int*)d_in[2];
    const int*   cand    = (const int*)d_in[3];
    float*       out     = (float*)d_out;

    cudaFuncSetAttribute(solve_kernel, cudaFuncAttributeMaxDynamicSharedMemorySize, SMEM_BYTES);

    setup_kernel<<<1, NTHR>>>(sel);
    solve_kernel<<<NCTA, NTHR, SMEM_BYTES>>>(weights, biases, cand, out);
}

// round 15
// speedup vs baseline: 4.6352x; 4.6352x over previous
#include <cuda_runtime.h>
#include <cstdint>

#define N 2304
#define BB 1024
#define FF 32
#define TEAM 72
#define NCTA (2 * TEAM)
#define NTHR 1024

#define CPS 9                      // chunks per step
#define CW 256                     // chunk extent along streamed dim
#define SLOT_FLOATS (32 * CW)      // 8192 floats = 32 KB
#define RING 6
#define DEPTH 5
#define TOTAL (31 * CPS)           // 279 chunks per team member
#define SMEM_BYTES ((RING * SLOT_FLOATS + N + 32 * 33) * 4)   // 210048

// device scratch (no allocation allowed)
__device__ float g_v[FF * N];
__device__ float g_z[FF * N];
__device__ float g_keep[FF * N];
__device__ float g_vsum[TEAM];
__device__ int   g_arrF[32 * TEAM];   // flag-array barriers (fwd)
__device__ int   g_arrB[32 * TEAM];   // flag-array barriers (bwd)
__device__ int   g_cntAll;

__global__ void setup_kernel(const int* __restrict__ sel) {
    int tid = threadIdx.x;
    for (int i = tid; i < FF * N; i += NTHR) g_keep[i] = 1.0f;
    for (int i = tid; i < 32 * TEAM; i += NTHR) { g_arrF[i] = 0; g_arrB[i] = 0; }
    if (tid == 0) g_cntAll = 0;
    __syncthreads();
    if (tid < 256) {
        int f = sel[3 * tid];
        int node = sel[3 * tid + 1] * 64 + sel[3 * tid + 2];
        g_keep[f * N + node] = 0.0f;
    }
}

// flag-array team barrier: no atomic serialization; warp0 polls 72 flags in parallel
__device__ __forceinline__ void teambar(int* arr, int step, int cta) {
    __threadfence();
    __syncthreads();
    if (threadIdx.x < 32) {
        volatile int* base = (volatile int*)arr + step * TEAM;
        int l = threadIdx.x;
        if (l == 0) base[cta] = 1;
        bool ok = false;
        do {
            int x = base[l] & base[l + 32];          // l+32 in [32,63] < 72
            if (l < 8) x &= base[l + 64];            // 64..71
            ok = __all_sync(0xffffffffu, x != 0);
        } while (!ok);
        __threadfence();
    }
    __syncthreads();
}

__device__ __forceinline__ void cpasync16(uint32_t dst, const void* src) {
    asm volatile("cp.async.cg.shared.global [%0], [%1], 16;" :: "r"(dst), "l"(src));
}
__device__ __forceinline__ void cpcommit() { asm volatile("cp.async.commit_group;"); }
__device__ __forceinline__ void cpwait4()  { asm volatile("cp.async.wait_group 4;" ::: "memory"); }
__device__ __forceinline__ void cpwait0()  { asm volatile("cp.async.wait_group 0;" ::: "memory"); }

// Persistent solver + fused final. 144 CTAs (1/SM), two teams of 72.
// CTAs 0..71:   forward  v_f = keep_f * (b_f + W[f-1] @ v_{f-1})   (32 rows each)
// CTAs 72..143: backward z_f = 1 + W[f]^T @ (keep_{f+1} * z_{f+1}) (32 cols each)
// Weights stream continuously via a cp.async 16B chunk pipeline (ring of
// 6 x 32KB, 5 in flight) that runs across step boundaries.
__global__ void __launch_bounds__(NTHR, 1)
solve_kernel(const float* __restrict__ W, const float* __restrict__ B,
             const int* __restrict__ cand, float* __restrict__ out)
{
    extern __shared__ float smem[];
    float* s_slot = smem;                      // RING x 8192 floats
    float* s_v    = smem + RING * SLOT_FLOATS; // N
    float* s_red  = s_v + N;                   // 32x33

    uint32_t sbase;
    asm("{ .reg .u64 t; cvta.to.shared.u64 t, %1; cvt.u32.u64 %0, t; }" : "=r"(sbase) : "l"(smem));

    int tid = threadIdx.x;
    int cta = blockIdx.x;
    int warp = tid >> 5, lane = tid & 31;

    if (cta < TEAM) {
        // ================= FORWARD TEAM =================
        int r0 = cta * 32;
        float myacc = 0.f;

        // chunk idx -> slab ff = idx/9 (W[ff] used by step f=ff+1), col block cc
        auto issue = [&](int idx) {
            int ff = idx / CPS, cc = idx - ff * CPS;
            const float* base = W + ((size_t)ff * N + r0) * N + cc * CW;
            uint32_t dst = sbase + (uint32_t)(idx % RING) * (SLOT_FLOATS * 4);
            #pragma unroll
            for (int k = 0; k < 2; ++k) {
                int e = tid + k * 1024;          // e = row*64 + q (row<32, q<64)
                int row = e >> 6, q = e & 63;
                cpasync16(dst + (uint32_t)e * 16, base + (size_t)row * N + q * 4);
            }
            cpcommit();
        };

        int issued = 0;
        #pragma unroll
        for (int i = 0; i < DEPTH; ++i) issue(issued++);

        if (tid < 32) {
            int row = r0 + tid;
            float v = g_keep[row] * B[row];
            g_v[row] = v;
            myacc += v;
        }
        teambar(g_arrF, 0, cta);

        for (int f = 1; f < FF; ++f) {
            for (int n = tid; n < N; n += NTHR) s_v[n] = g_v[(f - 1) * N + n];

            float acc = 0.f;
            int g0 = (f - 1) * CPS;
            #pragma unroll
            for (int c = 0; c < CPS; ++c) {
                if (issued < TOTAL) cpwait4(); else cpwait0();
                __syncthreads();                 // chunk g0+c visible; slot reuse safe
                if (issued < TOTAL) issue(issued++);

                const float4* wrow = (const float4*)(s_slot + ((g0 + c) % RING) * SLOT_FLOATS + warp * CW);
                const float4* vv   = (const float4*)(s_v + c * CW);
                float4 w0 = wrow[lane],      v0 = vv[lane];
                float4 w1 = wrow[lane + 32], v1 = vv[lane + 32];
                acc += w0.x * v0.x + w0.y * v0.y + w0.z * v0.z + w0.w * v0.w;
                acc += w1.x * v1.x + w1.y * v1.y + w1.z * v1.z + w1.w * v1.w;
            }
            #pragma unroll
            for (int o = 16; o; o >>= 1)
                acc += __shfl_xor_sync(0xffffffffu, acc, o);
            int ra = r0 + warp;                  // warp owns one row
            if (lane == 0) {
                float va = g_keep[f * N + ra] * (B[f * N + ra] + acc);
                g_v[f * N + ra] = va;
                myacc += va;
            }
            if (f < FF - 1) teambar(g_arrF, f, cta);
        }

        #pragma unroll
        for (int o = 16; o; o >>= 1) myacc += __shfl_xor_sync(0xffffffffu, myacc, o);
        if (lane == 0) s_red[warp] = myacc;
        __syncthreads();
        if (tid == 0) {
            float t = 0.f;
            #pragma unroll
            for (int w = 0; w < 32; ++w) t += s_red[w];
            g_vsum[cta] = t;
        }
    } else {
        // ================= BACKWARD TEAM =================
        int id = cta - TEAM;
        int c0 = id * 32;

        // chunk idx -> slab ff = 30 - idx/9 (step computes z_ff), row block cc
        auto issue = [&](int idx) {
            int ff = 30 - idx / CPS, cc = idx - (30 - ff) * CPS;
            const float* base = W + ((size_t)ff * N + cc * CW) * N + c0;
            uint32_t dst = sbase + (uint32_t)(idx % RING) * (SLOT_FLOATS * 4);
            #pragma unroll
            for (int k = 0; k < 2; ++k) {
                int e = tid + k * 1024;          // e = row*8 + part (row<256, part<8)
                int row = e >> 3, part = e & 7;
                cpasync16(dst + (uint32_t)e * 16, base + (size_t)row * N + part * 4);
            }
            cpcommit();
        };

        int issued = 0;
        #pragma unroll
        for (int i = 0; i < DEPTH; ++i) issue(issued++);

        if (tid < 32) g_z[31 * N + c0 + tid] = 1.0f;
        teambar(g_arrB, 0, id);

        for (int f = FF - 2; f >= 0; --f) {
            for (int n = tid; n < N; n += NTHR)
                s_v[n] = g_keep[(f + 1) * N + n] * g_z[(f + 1) * N + n];

            float p = 0.f;
            int g0 = (30 - f) * CPS;
            #pragma unroll
            for (int c = 0; c < CPS; ++c) {
                if (issued < TOTAL) cpwait4(); else cpwait0();
                __syncthreads();
                if (issued < TOTAL) issue(issued++);

                const float* sw = s_slot + ((g0 + c) % RING) * SLOT_FLOATS;
                const float* vv = s_v + c * CW;
                #pragma unroll
                for (int j = 0; j < 8; ++j) {    // row r = warp + 32*j within chunk
                    int r = warp + j * 32;
                    p += sw[r * 32 + lane] * vv[r];
                }
            }
            __syncthreads();                     // consumption done; s_red reuse safe
            s_red[lane * 33 + warp] = p;         // padded transpose
            __syncthreads();
            float q = s_red[warp * 33 + lane];   // warp w reduces col c0+w
            #pragma unroll
            for (int o = 16; o; o >>= 1)
                q += __shfl_xor_sync(0xffffffffu, q, o);
            if (lane == 0) g_z[f * N + c0 + warp] = 1.0f + q;
            if (f > 0) teambar(g_arrB, 31 - f, id);
        }
    }

    // ================= FUSED FINAL =================
    __threadfence();
    __syncthreads();
    if (tid == 0) atomicAdd(&g_cntAll, 1);
    if (cta == 0) {
        if (tid == 0) {
            volatile int* c = &g_cntAll;
            while (*c < NCTA) { }
            __threadfence();
        }
        __syncthreads();
        float t = (tid < TEAM) ? g_vsum[tid] : 0.f;
        if (tid < 128) {
            #pragma unroll
            for (int o = 16; o; o >>= 1) t += __shfl_xor_sync(0xffffffffu, t, o);
            if ((tid & 31) == 0) s_red[tid >> 5] = t;
        }
        __syncthreads();
        if (tid == 0) s_red[0] = s_red[0] + s_red[1] + s_red[2] + s_red[3];
        __syncthreads();
        float TOT = s_red[0];
        int cf = cand[3 * tid];
        int cn = cand[3 * tid + 1] * 64 + cand[3 * tid + 2];
        out[tid] = TOT - g_v[cf * N + cn] * g_z[cf * N + cn];
    }
}

extern "C" void kernel_launch(void* const* d_in, const int* in_sizes, int n_in,
                              void* d_out, int out_size) {
    const float* weights = (const float*)d_in[0];
    const float* biases  = (const float*)d_in[1];
    const int*   sel     = (const int*)d_in[2];
    const int*   cand    = (const int*)d_in[3];
    float*       out     = (float*)d_out;

    cudaFuncSetAttribute(solve_kernel, cudaFuncAttributeMaxDynamicSharedMemorySize, SMEM_BYTES);

    setup_kernel<<<1, NTHR>>>(sel);
    solve_kernel<<<NCTA, NTHR, SMEM_BYTES>>>(weights, biases, cand, out);
}

// round 16
// speedup vs baseline: 7.5607x; 1.6311x over previous
#include <cuda_runtime.h>
#include <cuda.h>
#include <cstdint>

#define N 2304
#define BB 1024
#define FF 32
#define TEAM 72
#define NCTA (2 * TEAM)
#define NTHR 1024

#define CPS 9                      // chunks per step
#define CW 256                     // chunk extent along streamed dim
#define SLOT_FLOATS (32 * CW)      // 8192 floats = 32 KB
#define SLOT_BYTES 32768
#define RING 5
#define DEPTH 4
#define TOTAL (31 * CPS)           // 279 chunks per team member

// smem float offsets
#define OFF_V    (RING * SLOT_FLOATS)           // 40960
#define OFF_RED  (OFF_V + N)                    // 43264
#define OFF_MBAR (OFF_RED + 1056)               // 44320 (x4 = 177280, 8B aligned)
#define SMEM_BYTES (OFF_MBAR * 4 + 64)          // 177344

// device scratch (no allocation allowed)
__device__ float g_v[FF * N];
__device__ float g_z[FF * N];
__device__ float g_keep[FF * N];
__device__ float g_vsum[TEAM];
__device__ int   g_cntF[64];
__device__ int   g_cntB[64];
__device__ int   g_cntAll;
__device__ __align__(128) CUtensorMap g_tmaps[2];   // [0]=fwd box(64x32), [1]=bwd box(32x256)

__global__ void setup_kernel(const int* __restrict__ sel) {
    int tid = threadIdx.x;
    for (int i = tid; i < FF * N; i += NTHR) g_keep[i] = 1.0f;
    if (tid < 64) { g_cntF[tid] = 0; g_cntB[tid] = 0; }
    if (tid == 64) g_cntAll = 0;
    __syncthreads();
    if (tid < 256) {
        int f = sel[3 * tid];
        int node = sel[3 * tid + 1] * 64 + sel[3 * tid + 2];
        g_keep[f * N + node] = 0.0f;
    }
}

__device__ __forceinline__ void teambar(int* cnt, int s) {
    __threadfence();
    __syncthreads();
    if (threadIdx.x == 0) {
        atomicAdd(&cnt[s], 1);
        volatile int* c = &cnt[s];
        while (*c < TEAM) { }
        __threadfence();
    }
    __syncthreads();
}

__device__ __forceinline__ void mbar_init(uint32_t mb, uint32_t cnt) {
    asm volatile("mbarrier.init.shared.b64 [%0], %1;" :: "r"(mb), "r"(cnt) : "memory");
}
__device__ __forceinline__ void mbar_expect(uint32_t mb, uint32_t bytes) {
    asm volatile("mbarrier.arrive.expect_tx.shared.b64 _, [%0], %1;" :: "r"(mb), "r"(bytes) : "memory");
}
__device__ __forceinline__ void mbar_wait(uint32_t mb, uint32_t ph) {
    asm volatile("{\n\t.reg .pred p;\n\tWL_%=:\n\t"
        "mbarrier.try_wait.parity.acquire.cta.shared::cta.b64 p, [%0], %1, 0x989680;\n\t"
        "@p bra.uni WD_%=;\n\tbra.uni WL_%=;\n\tWD_%=:\n\t}"
        :: "r"(mb), "r"(ph) : "memory");
}
// 3-D tensor TMA load gmem->smem, completion via mbarrier complete_tx
__device__ __forceinline__ void tma3d(uint32_t dst, const CUtensorMap* map,
                                      int x, int y, int z, uint32_t mb) {
    asm volatile("cp.async.bulk.tensor.3d.shared::cta.global.tile.mbarrier::complete_tx::bytes "
        "[%0], [%1, {%2, %3, %4}], [%5];"
        :: "r"(dst), "l"(map), "r"(x), "r"(y), "r"(z), "r"(mb) : "memory");
}

// Persistent solver + fused final. 144 CTAs (1/SM), two teams of 72.
// CTAs 0..71:   forward  v_f = keep_f * (b_f + W[f-1] @ v_{f-1})   (32 rows each)
// CTAs 72..143: backward z_f = 1 + W[f]^T @ (keep_{f+1} * z_{f+1}) (32 cols each)
// Weights stream via TENSOR TMA (engine-side, no LSU ops): ring of 5 x 32KB
// chunks, 4 in flight, running continuously across step barriers.
__global__ void __launch_bounds__(NTHR, 1)
solve_kernel(const CUtensorMap* __restrict__ maps,
             const float* __restrict__ B,
             const int* __restrict__ cand, float* __restrict__ out)
{
    extern __shared__ float smem[];
    float* s_slot = smem;
    float* s_v    = smem + OFF_V;
    float* s_red  = smem + OFF_RED;

    uint32_t sbase;
    asm("{ .reg .u64 t; cvta.to.shared.u64 t, %1; cvt.u32.u64 %0, t; }" : "=r"(sbase) : "l"(smem));
    uint32_t mbar = sbase + OFF_MBAR * 4;

    int tid = threadIdx.x;
    int cta = blockIdx.x;
    int warp = tid >> 5, lane = tid & 31;

    if (tid < RING) mbar_init(mbar + tid * 8, 1);
    __syncthreads();

    if (cta < TEAM) {
        // ================= FORWARD TEAM =================
        int r0 = cta * 32;
        float myacc = 0.f;
        const CUtensorMap* mapF = &maps[0];
        if (tid == 0) asm volatile("prefetch.tensormap [%0];" :: "l"(mapF));

        // thread0: chunk idx -> W[idx/9] rows r0..r0+31, cols (idx%9)*256..+255
        // slot layout: 4 sub-boxes of [32 rows x 64 floats] (8192 B each)
        auto issue = [&](int idx) {
            int slot = idx % RING;
            uint32_t mb = mbar + slot * 8;
            mbar_expect(mb, SLOT_BYTES);
            int ff = idx / CPS, cc = idx % CPS;
            uint32_t dst = sbase + (uint32_t)slot * SLOT_BYTES;
            #pragma unroll
            for (int q = 0; q < 4; ++q)
                tma3d(dst + q * 8192u, mapF, cc * CW + q * 64, r0, ff, mb);
        };

        int issued = 0;
        if (tid == 0)
            for (int i = 0; i < DEPTH; ++i) issue(i);
        issued = DEPTH;

        if (tid < 32) {
            int row = r0 + tid;
            float v = g_keep[row] * B[row];
            g_v[row] = v;
            myacc += v;
        }
        teambar(g_cntF, 0);

        for (int f = 1; f < FF; ++f) {
            for (int n = tid; n < N; n += NTHR) s_v[n] = g_v[(f - 1) * N + n];

            float acc = 0.f;
            int g0 = (f - 1) * CPS;
            #pragma unroll
            for (int c = 0; c < CPS; ++c) {
                int idx = g0 + c;
                if (tid == 0) mbar_wait(mbar + (idx % RING) * 8, (idx / RING) & 1);
                __syncthreads();                 // chunk visible; slot (idx-1) free
                if (tid == 0 && issued < TOTAL) issue(issued);
                issued++;

                const float* slot = s_slot + (idx % RING) * SLOT_FLOATS;
                const float4* vv  = (const float4*)(s_v + c * CW);
                #pragma unroll
                for (int j = 0; j < 2; ++j) {
                    int f4 = lane + j * 32;      // float4 index 0..63 of warp's row
                    int q = f4 >> 4, c4 = f4 & 15;
                    float4 w4 = *(const float4*)(slot + q * 2048 + warp * 64 + c4 * 4);
                    float4 v4 = vv[f4];
                    acc += w4.x * v4.x + w4.y * v4.y + w4.z * v4.z + w4.w * v4.w;
                }
            }
            #pragma unroll
            for (int o = 16; o; o >>= 1)
                acc += __shfl_xor_sync(0xffffffffu, acc, o);
            int ra = r0 + warp;                  // warp owns one row
            if (lane == 0) {
                float va = g_keep[f * N + ra] * (B[f * N + ra] + acc);
                g_v[f * N + ra] = va;
                myacc += va;
            }
            if (f < FF - 1) teambar(g_cntF, f);
        }

        #pragma unroll
        for (int o = 16; o; o >>= 1) myacc += __shfl_xor_sync(0xffffffffu, myacc, o);
        if (lane == 0) s_red[warp] = myacc;
        __syncthreads();
        if (tid == 0) {
            float t = 0.f;
            #pragma unroll
            for (int w = 0; w < 32; ++w) t += s_red[w];
            g_vsum[cta] = t;
        }
    } else {
        // ================= BACKWARD TEAM =================
        int id = cta - TEAM;
        int c0 = id * 32;
        const CUtensorMap* mapB2 = &maps[1];
        if (tid == 0) asm volatile("prefetch.tensormap [%0];" :: "l"(mapB2));

        // thread0: chunk idx -> W[30-idx/9] rows (idx%9)*256..+255, cols c0..c0+31
        // slot layout: 256 rows x 32 floats (128 B per row)
        auto issue = [&](int idx) {
            int slot = idx % RING;
            uint32_t mb = mbar + slot * 8;
            mbar_expect(mb, SLOT_BYTES);
            int ff = 30 - idx / CPS, cc = idx % CPS;
            tma3d(sbase + (uint32_t)slot * SLOT_BYTES, mapB2, c0, cc * CW, ff, mb);
        };

        int issued = 0;
        if (tid == 0)
            for (int i = 0; i < DEPTH; ++i) issue(i);
        issued = DEPTH;

        if (tid < 32) g_z[31 * N + c0 + tid] = 1.0f;
        teambar(g_cntB, 0);

        for (int f = FF - 2; f >= 0; --f) {
            for (int n = tid; n < N; n += NTHR)
                s_v[n] = g_keep[(f + 1) * N + n] * g_z[(f + 1) * N + n];

            float p = 0.f;
            int g0 = (30 - f) * CPS;
            #pragma unroll
            for (int c = 0; c < CPS; ++c) {
                int idx = g0 + c;
                if (tid == 0) mbar_wait(mbar + (idx % RING) * 8, (idx / RING) & 1);
                __syncthreads();
                if (tid == 0 && issued < TOTAL) issue(issued);
                issued++;

                const float* sw = s_slot + (idx % RING) * SLOT_FLOATS;
                const float* vv = s_v + c * CW;
                #pragma unroll
                for (int j = 0; j < 8; ++j) {    // row r = warp + 32*j within chunk
                    int r = warp + j * 32;
                    p += sw[r * 32 + lane] * vv[r];
                }
            }
            __syncthreads();                     // consumption done; s_red reuse safe
            s_red[lane * 33 + warp] = p;         // padded transpose
            __syncthreads();
            float q = s_red[warp * 33 + lane];   // warp w reduces col c0+w
            #pragma unroll
            for (int o = 16; o; o >>= 1)
                q += __shfl_xor_sync(0xffffffffu, q, o);
            if (lane == 0) g_z[f * N + c0 + warp] = 1.0f + q;
            if (f > 0) teambar(g_cntB, 31 - f);
        }
    }

    // ================= FUSED FINAL =================
    __threadfence();
    __syncthreads();
    if (tid == 0) atomicAdd(&g_cntAll, 1);
    if (cta == 0) {
        if (tid == 0) {
            volatile int* c = &g_cntAll;
            while (*c < NCTA) { }
            __threadfence();
        }
        __syncthreads();
        float t = (tid < TEAM) ? g_vsum[tid] : 0.f;
        if (tid < 128) {
            #pragma unroll
            for (int o = 16; o; o >>= 1) t += __shfl_xor_sync(0xffffffffu, t, o);
            if ((tid & 31) == 0) s_red[tid >> 5] = t;
        }
        __syncthreads();
        if (tid == 0) s_red[0] = s_red[0] + s_red[1] + s_red[2] + s_red[3];
        __syncthreads();
        float TOT = s_red[0];
        int cf = cand[3 * tid];
        int cn = cand[3 * tid + 1] * 64 + cand[3 * tid + 2];
        out[tid] = TOT - g_v[cf * N + cn] * g_z[cf * N + cn];
    }
}

// ---- host ----
typedef CUresult (*EncodeFn)(CUtensorMap*, CUtensorMapDataType, cuuint32_t, void*,
                             const cuuint64_t*, const cuuint64_t*, const cuuint32_t*,
                             const cuuint32_t*, CUtensorMapInterleave, CUtensorMapSwizzle,
                             CUtensorMapL2promotion, CUtensorMapFloatOOBfill);

extern "C" void kernel_launch(void* const* d_in, const int* in_sizes, int n_in,
                              void* d_out, int out_size) {
    const float* weights = (const float*)d_in[0];
    const float* biases  = (const float*)d_in[1];
    const int*   sel     = (const int*)d_in[2];
    const int*   cand    = (const int*)d_in[3];
    float*       out     = (float*)d_out;

    static EncodeFn enc = nullptr;
    if (!enc) {
        void* p = nullptr;
        cudaDriverEntryPointQueryResult st;
        cudaGetDriverEntryPoint("cuTensorMapEncodeTiled", &p, cudaEnableDefault, &st);
        enc = (EncodeFn)p;
    }

    static CUtensorMap h_maps[2];
    cuuint64_t dims[3] = {N, N, FF - 1};
    cuuint64_t strides[2] = {(cuuint64_t)N * 4, (cuuint64_t)N * N * 4};
    cuuint32_t es[3] = {1, 1, 1};
    cuuint32_t boxF[3] = {64, 32, 1};    // fwd: 256B inner x 32 rows
    cuuint32_t boxB[3] = {32, 256, 1};   // bwd: 128B inner x 256 rows
    enc(&h_maps[0], CU_TENSOR_MAP_DATA_TYPE_FLOAT32, 3, (void*)weights, dims, strides,
        boxF, es, CU_TENSOR_MAP_INTERLEAVE_NONE, CU_TENSOR_MAP_SWIZZLE_NONE,
        CU_TENSOR_MAP_L2_PROMOTION_L2_128B, CU_TENSOR_MAP_FLOAT_OOB_FILL_NONE);
    enc(&h_maps[1], CU_TENSOR_MAP_DATA_TYPE_FLOAT32, 3, (void*)weights, dims, strides,
        boxB, es, CU_TENSOR_MAP_INTERLEAVE_NONE, CU_TENSOR_MAP_SWIZZLE_NONE,
        CU_TENSOR_MAP_L2_PROMOTION_L2_128B, CU_TENSOR_MAP_FLOAT_OOB_FILL_NONE);
    cudaMemcpyToSymbolAsync(g_tmaps, h_maps, sizeof(h_maps), 0, cudaMemcpyHostToDevice, 0);

    void* mapsym = nullptr;
    cudaGetSymbolAddress(&mapsym, g_tmaps);
    const CUtensorMap* dmaps = (const CUtensorMap*)mapsym;

    cudaFuncSetAttribute(solve_kernel, cudaFuncAttributeMaxDynamicSharedMemorySize, SMEM_BYTES);

    setup_kernel<<<1, NTHR>>>(sel);
    solve_kernel<<<NCTA, NTHR, SMEM_BYTES>>>(dmaps, biases, cand, out);
}